// round 13
// baseline (speedup 1.0000x reference)
#include <cuda_runtime.h>

#define CHN   4
#define HHT   128
#define WWD   128
#define TT    50
#define TP    52          // padded t-stride: mult of 4 (LDS.128), conflict-free
#define SOP   52          // staging row stride (floats), float2 aligned
#define NBATCH 8
#define AW2   132         // bufA plane width/height (PAD=2 halo)
#define BW2   130         // bufB plane width/height (PAD=1 halo)
#define NPLANE (NBATCH*CHN)   // 32

// Padded ping-pong buffers: [plane][H2][W2][TT], zero halo.
__device__ float g_bufA[NPLANE * AW2 * AW2 * TT];
__device__ float g_bufB[NPLANE * BW2 * BW2 * TT];

typedef unsigned long long u64;

// Pre-duplicated weights in constant memory.
// c_w5d[tap*2+0]=(w0,w0,w1,w1), [tap*2+1]=(w2,w2,w3,w3), tap=(ci*K+kh)*K+kw
__constant__ ulonglong2 c_w5d[200];
__constant__ ulonglong2 c_w3d[72];
__device__ float4 g_wpack[272];

template <int K>
__device__ __forceinline__ ulonglong2 cwload(int i);
template <>
__device__ __forceinline__ ulonglong2 cwload<5>(int i) { return c_w5d[i]; }
template <>
__device__ __forceinline__ ulonglong2 cwload<3>(int i) { return c_w3d[i]; }

__device__ __forceinline__ void fma2(u64& d, u64 a, u64 b) {
    asm("fma.rn.f32x2 %0, %1, %2, %0;" : "+l"(d) : "l"(a), "l"(b));
}
__device__ __forceinline__ float2 upk(u64 v) {
    float2 f;
    f.x = __uint_as_float((unsigned)(v & 0xffffffffull));
    f.y = __uint_as_float((unsigned)(v >> 32));
    return f;
}

#define WAITG(n) asm volatile("cp.async.wait_group %0;" :: "n"(n) : "memory")

// Merged setup kernel: block 0 packs weights; blocks 1..64 zero buffer halos.
__global__ void setup_kernel(const float* __restrict__ w1,
                             const float* __restrict__ w2) {
    if (blockIdx.x == 0) {
        int tid = threadIdx.x;
        if (tid < 100) {
            float a = w1[tid], b = w1[100 + tid], c = w1[200 + tid], d = w1[300 + tid];
            g_wpack[tid * 2 + 0] = make_float4(a, a, b, b);
            g_wpack[tid * 2 + 1] = make_float4(c, c, d, d);
        }
        if (tid >= 128 && tid < 164) {
            int t = tid - 128;
            float a = w2[t], b = w2[36 + t], c = w2[72 + t], d = w2[108 + t];
            g_wpack[200 + t * 2 + 0] = make_float4(a, a, b, b);
            g_wpack[200 + t * 2 + 1] = make_float4(c, c, d, d);
        }
        return;
    }
    // halo zeroing (coalesced float2), one block per plane per buffer
    int bid = blockIdx.x - 1;
    float* buf;
    int W2, P, plane;
    if (bid < NPLANE) { buf = g_bufA; W2 = AW2; P = 2; plane = bid; }
    else              { buf = g_bufB; W2 = BW2; P = 1; plane = bid - NPLANE; }
    const int H2 = W2;
    float2* base = reinterpret_cast<float2*>(buf + (long)plane * H2 * W2 * TT);
    const int strip = P * W2 * TT / 2;
    const float2 z = make_float2(0.f, 0.f);
    float2* bot = base + (long)(H2 - P) * W2 * (TT / 2);
    for (int i = threadIdx.x; i < strip; i += blockDim.x) {
        base[i] = z;
        bot[i]  = z;
    }
    const int ch = P * TT / 2;
    const int nrows = H2 - 2 * P;
    for (int idx = threadIdx.x; idx < nrows * 2 * ch; idx += blockDim.x) {
        int row = idx / (2 * ch);
        int rem = idx - row * (2 * ch);
        int side = rem / ch;
        int off  = rem - side * ch;
        float2* p = base + (long)(P + row) * W2 * (TT / 2)
                         + (side ? (W2 - P) * (TT / 2) : 0);
        p[off] = z;
    }
}

// ---------------------------------------------------------------------------
// Standalone alpha-PSP (layer 1): unpadded input -> padded bufA interior.
// ---------------------------------------------------------------------------
#define PW_PAD 53

__global__ void __launch_bounds__(128, 8) psp_kernel(const float* __restrict__ in,
                                                     float* __restrict__ out,
                                                     float r, float coef) {
    __shared__ float sm[4 * 32 * PW_PAD];
    const int lane = threadIdx.x & 31;
    const int wrp  = threadIdx.x >> 5;
    const int h    = blockIdx.x;
    const int nc   = blockIdx.y;
    float* ws = sm + wrp * 32 * PW_PAD;
    const float* g = in + (((long)nc * HHT + h) * WWD + wrp * 32) * TT;
    float* o = out + (((long)nc * AW2 + h + 2) * AW2 + (wrp * 32 + 2)) * TT;
#pragma unroll
    for (int w = 0; w < 32; ++w) {
        ws[w * PW_PAD + lane] = g[w * TT + lane];
        if (lane < TT - 32) ws[w * PW_PAD + 32 + lane] = g[w * TT + 32 + lane];
    }
    __syncwarp();
    float* row = ws + lane * PW_PAD;
    float s1 = 0.f, s2 = 0.f;
#pragma unroll
    for (int t = 0; t < TT; ++t) {
        float x = row[t];
        row[t] = coef * s2;
        s1 = fmaf(r, s1, x);
        s2 = fmaf(r, s2, r * s1);
    }
    __syncwarp();
#pragma unroll
    for (int w = 0; w < 32; ++w) {
        o[w * TT + lane] = ws[w * PW_PAD + lane];
        if (lane < TT - 32) o[w * TT + 32 + lane] = ws[w * PW_PAD + 32 + lane];
    }
}

// ---------------------------------------------------------------------------
// Fused conv(KxK, 4->4) + spike epilogue; 2-output-row register blocking.
// PIPE=1 (conv5): 2-buffer cp.async pipeline over ci.
// PIPE=0 (conv3): ALL 4 ci buffers filled up front; ONE wait+barrier, then
//                 the whole 4-ci FMA loop runs with no barriers at all.
// Thread (w=lane, t-quad t0=4*wrp) x 2 output rows x 4 co, FFMA2.
// ---------------------------------------------------------------------------
template <int K, int PIPE, int EPI, int INW2, int OUTW2, int OUTPAD>
__global__ void __launch_bounds__(416, 2)
conv_fused_kernel(const float* __restrict__ in, float* __restrict__ out,
                  float rR, float cR, float theta, float rP, float cP) {
    constexpr int WH    = 32 + (K - 1);
    constexpr int NR    = K + 1;            // input rows per stage (2 outputs)
    constexpr int STAGE = NR * WH * TP;

    extern __shared__ float sm[];
    const unsigned smem_base = (unsigned)__cvta_generic_to_shared(sm);

    const int tid  = threadIdx.x;
    const int lane = tid & 31;
    const int wrp  = tid >> 5;
    const int w0   = blockIdx.x * 32;
    const int h0   = blockIdx.y * 2;        // first output row (padded coords)
    const int n    = blockIdx.z;
    const int t0   = wrp * 4;

    // unconditional async fill of buffer `buf` with channel ci
    auto fill = [&](int buf, int ci) {
        if (lane < 25) {
            const unsigned dstb = smem_base + buf * (STAGE * 4) + lane * 8;
            const int nc = n * CHN + ci;
#pragma unroll
            for (int r = 0; r < NR; ++r) {
                const char* srcb = (const char*)(in +
                    (((long)nc * INW2 + h0 + r) * INW2 + w0) * TT) + lane * 8;
#pragma unroll
                for (int rr = 0; rr < 3; ++rr) {
                    const int wr = wrp + rr * 13;
                    if (wr < WH) {
                        asm volatile("cp.async.ca.shared.global [%0], [%1], 8;"
                                     :: "r"(dstb + (r * WH + wr) * (TP * 4)),
                                        "l"(srcb + wr * (TT * 4)) : "memory");
                    }
                }
            }
        }
        asm volatile("cp.async.commit_group;" ::: "memory");
    };

    u64 acc[2][4][2];   // [hs][co][(t0,t0+1)|(t0+2,t0+3)]
#pragma unroll
    for (int s = 0; s < 2; ++s)
#pragma unroll
        for (int c = 0; c < 4; ++c) { acc[s][c][0] = 0ull; acc[s][c][1] = 0ull; }

    // compute one ci from smem buffer p
    auto compute = [&](const float* s_in, int ci) {
#pragma unroll
        for (int kw = 0; kw < K; ++kw) {
            const float* colp = s_in + (lane + kw) * TP + t0;
            ulonglong2 iv[NR];
#pragma unroll
            for (int r = 0; r < NR; ++r)
                iv[r] = *reinterpret_cast<const ulonglong2*>(colp + r * WH * TP);
#pragma unroll
            for (int r = 0; r < NR; ++r) {
                if (r < K) {        // output row 0: kh = r
                    const int tap = (ci * K + r) * K + kw;
                    const ulonglong2 wa = cwload<K>(tap * 2);
                    const ulonglong2 wb = cwload<K>(tap * 2 + 1);
                    fma2(acc[0][0][0], iv[r].x, wa.x);
                    fma2(acc[0][0][1], iv[r].y, wa.x);
                    fma2(acc[0][1][0], iv[r].x, wa.y);
                    fma2(acc[0][1][1], iv[r].y, wa.y);
                    fma2(acc[0][2][0], iv[r].x, wb.x);
                    fma2(acc[0][2][1], iv[r].y, wb.x);
                    fma2(acc[0][3][0], iv[r].x, wb.y);
                    fma2(acc[0][3][1], iv[r].y, wb.y);
                }
                if (r >= 1) {       // output row 1: kh = r-1 (same LDC, CSE)
                    const int tap = (ci * K + (r - 1)) * K + kw;
                    const ulonglong2 wa = cwload<K>(tap * 2);
                    const ulonglong2 wb = cwload<K>(tap * 2 + 1);
                    fma2(acc[1][0][0], iv[r].x, wa.x);
                    fma2(acc[1][0][1], iv[r].y, wa.x);
                    fma2(acc[1][1][0], iv[r].x, wa.y);
                    fma2(acc[1][1][1], iv[r].y, wa.y);
                    fma2(acc[1][2][0], iv[r].x, wb.x);
                    fma2(acc[1][2][1], iv[r].y, wb.x);
                    fma2(acc[1][3][0], iv[r].x, wb.y);
                    fma2(acc[1][3][1], iv[r].y, wb.y);
                }
            }
        }
    };

    if (PIPE) {
        // 2-buffer pipeline (conv5)
        fill(0, 0);
        WAITG(0);
        __syncthreads();
#pragma unroll
        for (int ci = 0; ci < CHN; ++ci) {
            if (ci < CHN - 1) fill((ci + 1) & 1, ci + 1);
            compute(sm + (ci & 1) * STAGE, ci);
            if (ci < CHN - 1) {
                WAITG(0);
                __syncthreads();
            }
        }
    } else {
        // monolithic fill (conv3): everything in flight up front, one barrier
        fill(0, 0);
        fill(1, 1);
        fill(2, 2);
        fill(3, 3);
        WAITG(0);
        __syncthreads();
#pragma unroll
        for (int ci = 0; ci < CHN; ++ci)
            compute(sm + ci * STAGE, ci);
    }
    __syncthreads();

    // stage conv results: s_out[(hs*4+co)][w][SOP]
    float* s_out = sm;   // overlay: 8*32*52*4 = 53248 B, fits both layouts
#pragma unroll
    for (int hs = 0; hs < 2; ++hs)
#pragma unroll
        for (int co = 0; co < 4; ++co) {
            float* p = s_out + ((hs * 4 + co) * 32 + lane) * SOP + t0;
            float2 a = upk(acc[hs][co][0]);
            *reinterpret_cast<float2*>(p) = a;
            if (t0 + 2 < TT) {
                float2 b = upk(acc[hs][co][1]);
                *reinterpret_cast<float2*>(p + 2) = b;
            }
        }
    __syncthreads();

    // fused spike-dynamics epilogue: 256 pixels (2hs x 4co x 32w)
    if (tid < 256) {
        const int hs = tid >> 7;
        const int co = (tid >> 5) & 3;
        const int w  = tid & 31;
        float* row = s_out + ((hs * 4 + co) * 32 + w) * SOP;
        float sd1 = 0.f, sd2 = 0.f, sp1 = 0.f, sp2 = 0.f;
#pragma unroll
        for (int t = 0; t < TT; ++t) {
            float m = fmaf(cR, sd2, row[t]);
            float s = (m >= theta) ? 1.f : 0.f;
            sd1 = fmaf(rR, sd1, s);
            sd2 = fmaf(rR, sd2, rR * sd1);
            if (EPI == 0) {
                row[t] = cP * sp2;
                sp1 = fmaf(rP, sp1, s);
                sp2 = fmaf(rP, sp2, rP * sp1);
            } else {
                row[t] = s;
            }
        }
    }
    __syncthreads();

    // structured coalesced store: float2, warp-per-w-row, 2 output rows
    if (lane < 25) {
#pragma unroll
        for (int hs = 0; hs < 2; ++hs)
#pragma unroll
            for (int co = 0; co < 4; ++co) {
                const float2* s2 = reinterpret_cast<const float2*>(
                    s_out + (hs * 4 + co) * 32 * SOP);
                float2* g2 = reinterpret_cast<float2*>(out +
                    (((long)(n * CHN + co) * OUTW2 + h0 + hs + OUTPAD) * OUTW2 +
                     (w0 + OUTPAD)) * TT);
#pragma unroll
                for (int rr = 0; rr < 3; ++rr) {
                    const int w = wrp + rr * 13;
                    if (w < 32) g2[w * (TT / 2) + lane] = s2[w * (SOP / 2) + lane];
                }
            }
    }
}

// ---------------------------------------------------------------------------

extern "C" void kernel_launch(void* const* d_in, const int* in_sizes, int n_in,
                              void* d_out, int out_size) {
    const float* x  = (const float*)d_in[0];
    const float* w1 = (const float*)d_in[1];
    const float* w2 = (const float*)d_in[2];
    float* outp = (float*)d_out;

    float *bufA, *bufB;
    cudaGetSymbolAddress((void**)&bufA, g_bufA);
    cudaGetSymbolAddress((void**)&bufB, g_bufB);
    float4* wpack;
    cudaGetSymbolAddress((void**)&wpack, g_wpack);

    const int SMEM5 = 2 * 6 * 36 * TP * 4;   // 89856 B  -> 2 blocks/SM
    const int SMEM3 = 4 * 4 * 34 * TP * 4;   // 113152 B -> 2 blocks/SM (226.3KB)
    cudaFuncSetAttribute((const void*)conv_fused_kernel<5, 1, 0, AW2, BW2, 1>,
                         cudaFuncAttributeMaxDynamicSharedMemorySize, SMEM5);
    cudaFuncSetAttribute((const void*)conv_fused_kernel<3, 0, 1, BW2, WWD, 0>,
                         cudaFuncAttributeMaxDynamicSharedMemorySize, SMEM3);

    const float r1  = (float)0.36787944117144233;   // exp(-1/tau1)
    const float cP1 = (float)2.718281828459045;     // e/tau1
    const float rR1 = (float)0.36787944117144233;   // exp(-1/tauRef1)
    const float cR1 = (float)(-54.365636569180902); // -scaleRef*theta1*e/tauRef1
    const float th1 = 20.0f;
    const float r2  = (float)0.6065306597126334;    // exp(-1/tau2)
    const float cP2 = (float)1.3591409142295225;    // e/tau2
    const float rR2 = (float)0.6065306597126334;    // exp(-1/tauRef2)
    const float cR2 = (float)(-54.365636569180902); // -scaleRef*theta2*e/tauRef2
    const float th2 = 40.0f;

    dim3 pgrid(HHT, NPLANE);                    // (128, 32)
    dim3 cgrid(WWD / 32, HHT / 2, NBATCH);      // (4,64,8) = 2048 blocks

    setup_kernel<<<1 + 2 * NPLANE, 256>>>(w1, w2);   // weights + halo zeroing
    cudaMemcpyToSymbolAsync(c_w5d, wpack, 200 * sizeof(float4), 0,
                            cudaMemcpyDeviceToDevice, 0);
    cudaMemcpyToSymbolAsync(c_w3d, wpack + 200, 72 * sizeof(float4), 0,
                            cudaMemcpyDeviceToDevice, 0);

    psp_kernel<<<pgrid, 128>>>(x, bufA, r1, cP1);
    conv_fused_kernel<5, 1, 0, AW2, BW2, 1><<<cgrid, 416, SMEM5>>>(bufA, bufB,
                                                    rR1, cR1, th1, r2, cP2);
    conv_fused_kernel<3, 0, 1, BW2, WWD, 0><<<cgrid, 416, SMEM3>>>(bufB, outp,
                                                    rR2, cR2, th2, 0.f, 0.f);
}

// round 14
// speedup vs baseline: 1.0551x; 1.0551x over previous
#include <cuda_runtime.h>

#define CHN   4
#define HHT   128
#define WWD   128
#define TT    50
#define TP    52          // padded t-stride: mult of 4 (LDS.128), conflict-free
#define SOP   52          // staging row stride (floats), float2 aligned
#define NBATCH 8
#define AW2   132         // bufA plane width/height (PAD=2 halo)
#define BW2   130         // bufB plane width/height (PAD=1 halo)
#define NPLANE (NBATCH*CHN)   // 32

// Padded ping-pong buffers: [plane][H2][W2][TT], zero halo.
__device__ float g_bufA[NPLANE * AW2 * AW2 * TT];
__device__ float g_bufB[NPLANE * BW2 * BW2 * TT];

typedef unsigned long long u64;

// Pre-duplicated weights in constant memory.
// c_w5d[tap*2+0]=(w0,w0,w1,w1), [tap*2+1]=(w2,w2,w3,w3), tap=(ci*K+kh)*K+kw
__constant__ ulonglong2 c_w5d[200];
__constant__ ulonglong2 c_w3d[72];
__device__ float4 g_wpack[272];

template <int K>
__device__ __forceinline__ ulonglong2 cwload(int i);
template <>
__device__ __forceinline__ ulonglong2 cwload<5>(int i) { return c_w5d[i]; }
template <>
__device__ __forceinline__ ulonglong2 cwload<3>(int i) { return c_w3d[i]; }

__device__ __forceinline__ void fma2(u64& d, u64 a, u64 b) {
    asm("fma.rn.f32x2 %0, %1, %2, %0;" : "+l"(d) : "l"(a), "l"(b));
}
__device__ __forceinline__ float2 upk(u64 v) {
    float2 f;
    f.x = __uint_as_float((unsigned)(v & 0xffffffffull));
    f.y = __uint_as_float((unsigned)(v >> 32));
    return f;
}

#define WAITG(n) asm volatile("cp.async.wait_group %0;" :: "n"(n) : "memory")

// Merged setup kernel: block 0 packs weights; blocks 1..64 zero buffer halos.
__global__ void setup_kernel(const float* __restrict__ w1,
                             const float* __restrict__ w2) {
    if (blockIdx.x == 0) {
        int tid = threadIdx.x;
        if (tid < 100) {
            float a = w1[tid], b = w1[100 + tid], c = w1[200 + tid], d = w1[300 + tid];
            g_wpack[tid * 2 + 0] = make_float4(a, a, b, b);
            g_wpack[tid * 2 + 1] = make_float4(c, c, d, d);
        }
        if (tid >= 128 && tid < 164) {
            int t = tid - 128;
            float a = w2[t], b = w2[36 + t], c = w2[72 + t], d = w2[108 + t];
            g_wpack[200 + t * 2 + 0] = make_float4(a, a, b, b);
            g_wpack[200 + t * 2 + 1] = make_float4(c, c, d, d);
        }
        return;
    }
    int bid = blockIdx.x - 1;
    float* buf;
    int W2, P, plane;
    if (bid < NPLANE) { buf = g_bufA; W2 = AW2; P = 2; plane = bid; }
    else              { buf = g_bufB; W2 = BW2; P = 1; plane = bid - NPLANE; }
    const int H2 = W2;
    float2* base = reinterpret_cast<float2*>(buf + (long)plane * H2 * W2 * TT);
    const int strip = P * W2 * TT / 2;
    const float2 z = make_float2(0.f, 0.f);
    float2* bot = base + (long)(H2 - P) * W2 * (TT / 2);
    for (int i = threadIdx.x; i < strip; i += blockDim.x) {
        base[i] = z;
        bot[i]  = z;
    }
    const int ch = P * TT / 2;
    const int nrows = H2 - 2 * P;
    for (int idx = threadIdx.x; idx < nrows * 2 * ch; idx += blockDim.x) {
        int row = idx / (2 * ch);
        int rem = idx - row * (2 * ch);
        int side = rem / ch;
        int off  = rem - side * ch;
        float2* p = base + (long)(P + row) * W2 * (TT / 2)
                         + (side ? (W2 - P) * (TT / 2) : 0);
        p[off] = z;
    }
}

// ---------------------------------------------------------------------------
// Standalone alpha-PSP (layer 1): unpadded input -> padded bufA interior.
// ---------------------------------------------------------------------------
#define PW_PAD 53

__global__ void __launch_bounds__(128, 8) psp_kernel(const float* __restrict__ in,
                                                     float* __restrict__ out,
                                                     float r, float coef) {
    __shared__ float sm[4 * 32 * PW_PAD];
    const int lane = threadIdx.x & 31;
    const int wrp  = threadIdx.x >> 5;
    const int h    = blockIdx.x;
    const int nc   = blockIdx.y;
    float* ws = sm + wrp * 32 * PW_PAD;
    const float* g = in + (((long)nc * HHT + h) * WWD + wrp * 32) * TT;
    float* o = out + (((long)nc * AW2 + h + 2) * AW2 + (wrp * 32 + 2)) * TT;
#pragma unroll
    for (int w = 0; w < 32; ++w) {
        ws[w * PW_PAD + lane] = g[w * TT + lane];
        if (lane < TT - 32) ws[w * PW_PAD + 32 + lane] = g[w * TT + 32 + lane];
    }
    __syncwarp();
    float* row = ws + lane * PW_PAD;
    float s1 = 0.f, s2 = 0.f;
#pragma unroll
    for (int t = 0; t < TT; ++t) {
        float x = row[t];
        row[t] = coef * s2;
        s1 = fmaf(r, s1, x);
        s2 = fmaf(r, s2, r * s1);
    }
    __syncwarp();
#pragma unroll
    for (int w = 0; w < 32; ++w) {
        o[w * TT + lane] = ws[w * PW_PAD + lane];
        if (lane < TT - 32) o[w * TT + 32 + lane] = ws[w * PW_PAD + 32 + lane];
    }
}

// ---------------------------------------------------------------------------
// Fused conv(KxK, 4->4) + spike epilogue; 2-output-row register blocking.
// NBUF=2 (conv5): classic double buffer, wait_group 0 each round.
// NBUF=3 (conv3): 3-stage ring, 2 ci in flight, wait_group 1 -> the needed
//                 buffer's fill has long completed when its barrier is hit.
// Thread (w=lane, t-quad t0=4*wrp) x 2 output rows x 4 co, FFMA2.
// ---------------------------------------------------------------------------
template <int K, int NBUF, int EPI, int INW2, int OUTW2, int OUTPAD>
__global__ void __launch_bounds__(416, 2)
conv_fused_kernel(const float* __restrict__ in, float* __restrict__ out,
                  float rR, float cR, float theta, float rP, float cP) {
    constexpr int WH    = 32 + (K - 1);
    constexpr int NR    = K + 1;            // input rows per stage (2 outputs)
    constexpr int STAGE = NR * WH * TP;

    extern __shared__ float sm[];
    const unsigned smem_base = (unsigned)__cvta_generic_to_shared(sm);

    const int tid  = threadIdx.x;
    const int lane = tid & 31;
    const int wrp  = tid >> 5;
    const int w0   = blockIdx.x * 32;
    const int h0   = blockIdx.y * 2;        // first output row (padded coords)
    const int n    = blockIdx.z;
    const int t0   = wrp * 4;

    // unconditional async fill of buffer `buf` with channel ci (own group)
    auto fill = [&](int buf, int ci) {
        if (lane < 25) {
            const unsigned dstb = smem_base + buf * (STAGE * 4) + lane * 8;
            const int nc = n * CHN + ci;
#pragma unroll
            for (int r = 0; r < NR; ++r) {
                const char* srcb = (const char*)(in +
                    (((long)nc * INW2 + h0 + r) * INW2 + w0) * TT) + lane * 8;
#pragma unroll
                for (int rr = 0; rr < 3; ++rr) {
                    const int wr = wrp + rr * 13;
                    if (wr < WH) {
                        asm volatile("cp.async.ca.shared.global [%0], [%1], 8;"
                                     :: "r"(dstb + (r * WH + wr) * (TP * 4)),
                                        "l"(srcb + wr * (TT * 4)) : "memory");
                    }
                }
            }
        }
        asm volatile("cp.async.commit_group;" ::: "memory");
    };

    u64 acc[2][4][2];   // [hs][co][(t0,t0+1)|(t0+2,t0+3)]
#pragma unroll
    for (int s = 0; s < 2; ++s)
#pragma unroll
        for (int c = 0; c < 4; ++c) { acc[s][c][0] = 0ull; acc[s][c][1] = 0ull; }

    auto compute = [&](const float* s_in, int ci) {
#pragma unroll
        for (int kw = 0; kw < K; ++kw) {
            const float* colp = s_in + (lane + kw) * TP + t0;
            ulonglong2 iv[NR];
#pragma unroll
            for (int r = 0; r < NR; ++r)
                iv[r] = *reinterpret_cast<const ulonglong2*>(colp + r * WH * TP);
#pragma unroll
            for (int r = 0; r < NR; ++r) {
                if (r < K) {        // output row 0: kh = r
                    const int tap = (ci * K + r) * K + kw;
                    const ulonglong2 wa = cwload<K>(tap * 2);
                    const ulonglong2 wb = cwload<K>(tap * 2 + 1);
                    fma2(acc[0][0][0], iv[r].x, wa.x);
                    fma2(acc[0][0][1], iv[r].y, wa.x);
                    fma2(acc[0][1][0], iv[r].x, wa.y);
                    fma2(acc[0][1][1], iv[r].y, wa.y);
                    fma2(acc[0][2][0], iv[r].x, wb.x);
                    fma2(acc[0][2][1], iv[r].y, wb.x);
                    fma2(acc[0][3][0], iv[r].x, wb.y);
                    fma2(acc[0][3][1], iv[r].y, wb.y);
                }
                if (r >= 1) {       // output row 1: kh = r-1 (same LDC, CSE)
                    const int tap = (ci * K + (r - 1)) * K + kw;
                    const ulonglong2 wa = cwload<K>(tap * 2);
                    const ulonglong2 wb = cwload<K>(tap * 2 + 1);
                    fma2(acc[1][0][0], iv[r].x, wa.x);
                    fma2(acc[1][0][1], iv[r].y, wa.x);
                    fma2(acc[1][1][0], iv[r].x, wa.y);
                    fma2(acc[1][1][1], iv[r].y, wa.y);
                    fma2(acc[1][2][0], iv[r].x, wb.x);
                    fma2(acc[1][2][1], iv[r].y, wb.x);
                    fma2(acc[1][3][0], iv[r].x, wb.y);
                    fma2(acc[1][3][1], iv[r].y, wb.y);
                }
            }
        }
    };

    if (NBUF == 2) {
        // double buffer (conv5)
        fill(0, 0);
        WAITG(0);
        __syncthreads();
#pragma unroll
        for (int ci = 0; ci < CHN; ++ci) {
            if (ci < CHN - 1) fill((ci + 1) & 1, ci + 1);
            compute(sm + (ci & 1) * STAGE, ci);
            if (ci < CHN - 1) {
                WAITG(0);
                __syncthreads();
            }
        }
    } else {
        // 3-stage ring (conv3): keep 2 ci in flight, wait leaves 1 pending
        fill(0, 0);
        fill(1, 1);
        WAITG(1);          // buffer 0 complete, buffer 1 may be in flight
        __syncthreads();
#pragma unroll
        for (int ci = 0; ci < CHN; ++ci) {
            if (ci + 2 < CHN) fill((ci + 2) % 3, ci + 2);
            compute(sm + (ci % 3) * STAGE, ci);
            if (ci < CHN - 1) {
                if (ci + 2 < CHN) WAITG(1);  // next buffer done, one in flight
                else              WAITG(0);  // last fill must fully drain
                __syncthreads();
            }
        }
    }
    __syncthreads();

    // stage conv results: s_out[(hs*4+co)][w][SOP]
    float* s_out = sm;   // overlay: 8*32*52*4 = 53248 B, barrier above guards
#pragma unroll
    for (int hs = 0; hs < 2; ++hs)
#pragma unroll
        for (int co = 0; co < 4; ++co) {
            float* p = s_out + ((hs * 4 + co) * 32 + lane) * SOP + t0;
            float2 a = upk(acc[hs][co][0]);
            *reinterpret_cast<float2*>(p) = a;
            if (t0 + 2 < TT) {
                float2 b = upk(acc[hs][co][1]);
                *reinterpret_cast<float2*>(p + 2) = b;
            }
        }
    __syncthreads();

    // fused spike-dynamics epilogue: 256 pixels (2hs x 4co x 32w)
    if (tid < 256) {
        const int hs = tid >> 7;
        const int co = (tid >> 5) & 3;
        const int w  = tid & 31;
        float* row = s_out + ((hs * 4 + co) * 32 + w) * SOP;
        float sd1 = 0.f, sd2 = 0.f, sp1 = 0.f, sp2 = 0.f;
#pragma unroll
        for (int t = 0; t < TT; ++t) {
            float m = fmaf(cR, sd2, row[t]);
            float s = (m >= theta) ? 1.f : 0.f;
            sd1 = fmaf(rR, sd1, s);
            sd2 = fmaf(rR, sd2, rR * sd1);
            if (EPI == 0) {
                row[t] = cP * sp2;
                sp1 = fmaf(rP, sp1, s);
                sp2 = fmaf(rP, sp2, rP * sp1);
            } else {
                row[t] = s;
            }
        }
    }
    __syncthreads();

    // structured coalesced store: float2, warp-per-w-row, 2 output rows
    if (lane < 25) {
#pragma unroll
        for (int hs = 0; hs < 2; ++hs)
#pragma unroll
            for (int co = 0; co < 4; ++co) {
                const float2* s2 = reinterpret_cast<const float2*>(
                    s_out + (hs * 4 + co) * 32 * SOP);
                float2* g2 = reinterpret_cast<float2*>(out +
                    (((long)(n * CHN + co) * OUTW2 + h0 + hs + OUTPAD) * OUTW2 +
                     (w0 + OUTPAD)) * TT);
#pragma unroll
                for (int rr = 0; rr < 3; ++rr) {
                    const int w = wrp + rr * 13;
                    if (w < 32) g2[w * (TT / 2) + lane] = s2[w * (SOP / 2) + lane];
                }
            }
    }
}

// ---------------------------------------------------------------------------

extern "C" void kernel_launch(void* const* d_in, const int* in_sizes, int n_in,
                              void* d_out, int out_size) {
    const float* x  = (const float*)d_in[0];
    const float* w1 = (const float*)d_in[1];
    const float* w2 = (const float*)d_in[2];
    float* outp = (float*)d_out;

    float *bufA, *bufB;
    cudaGetSymbolAddress((void**)&bufA, g_bufA);
    cudaGetSymbolAddress((void**)&bufB, g_bufB);
    float4* wpack;
    cudaGetSymbolAddress((void**)&wpack, g_wpack);

    const int SMEM5 = 2 * 6 * 36 * TP * 4;   // 89856 B -> 2 blocks/SM
    const int SMEM3 = 3 * 4 * 34 * TP * 4;   // 84864 B -> 2 blocks/SM
    cudaFuncSetAttribute((const void*)conv_fused_kernel<5, 2, 0, AW2, BW2, 1>,
                         cudaFuncAttributeMaxDynamicSharedMemorySize, SMEM5);
    cudaFuncSetAttribute((const void*)conv_fused_kernel<3, 3, 1, BW2, WWD, 0>,
                         cudaFuncAttributeMaxDynamicSharedMemorySize, SMEM3);

    const float r1  = (float)0.36787944117144233;   // exp(-1/tau1)
    const float cP1 = (float)2.718281828459045;     // e/tau1
    const float rR1 = (float)0.36787944117144233;   // exp(-1/tauRef1)
    const float cR1 = (float)(-54.365636569180902); // -scaleRef*theta1*e/tauRef1
    const float th1 = 20.0f;
    const float r2  = (float)0.6065306597126334;    // exp(-1/tau2)
    const float cP2 = (float)1.3591409142295225;    // e/tau2
    const float rR2 = (float)0.6065306597126334;    // exp(-1/tauRef2)
    const float cR2 = (float)(-54.365636569180902); // -scaleRef*theta2*e/tauRef2
    const float th2 = 40.0f;

    dim3 pgrid(HHT, NPLANE);                    // (128, 32)
    dim3 cgrid(WWD / 32, HHT / 2, NBATCH);      // (4,64,8) = 2048 blocks

    setup_kernel<<<1 + 2 * NPLANE, 256>>>(w1, w2);   // weights + halo zeroing
    cudaMemcpyToSymbolAsync(c_w5d, wpack, 200 * sizeof(float4), 0,
                            cudaMemcpyDeviceToDevice, 0);
    cudaMemcpyToSymbolAsync(c_w3d, wpack + 200, 72 * sizeof(float4), 0,
                            cudaMemcpyDeviceToDevice, 0);

    psp_kernel<<<pgrid, 128>>>(x, bufA, r1, cP1);
    conv_fused_kernel<5, 2, 0, AW2, BW2, 1><<<cgrid, 416, SMEM5>>>(bufA, bufB,
                                                    rR1, cR1, th1, r2, cP2);
    conv_fused_kernel<3, 3, 1, BW2, WWD, 0><<<cgrid, 416, SMEM3>>>(bufB, outp,
                                                    rR2, cR2, th2, 0.f, 0.f);
}